// round 1
// baseline (speedup 1.0000x reference)
#include <cuda_runtime.h>

// VectorQuantizer: x [16,256,32,32] f32, codebook [4096,256] f32
// out [16,256,32,32] f32 = codebook[argmin_k ||x_token - c_k||^2] scattered back.
//
// Pipeline:
//   1) csq_kernel:   g_csq[k] = ||c_k||^2
//   2) argmin_kernel: per 64-token tile, loop all 4096 codes in 64-code tiles,
//      register-blocked 4x4 microtile fp32 GEMM (dot products), score =
//      csq - 2*dot (||x||^2 constant per token, dropped), running argmin.
//   3) gather_kernel: out[b,d,h,w] = codebook[idx[n]][d], coalesced on output.

#define NTOK   16384
#define DIM    256
#define KCODES 4096
#define HW     1024   // H*W
#define BT     64     // tokens per block
#define BC     64     // codes per tile
#define DC     16     // D chunk

__device__ float g_csq[KCODES];
__device__ int   g_idx[NTOK];

__global__ void csq_kernel(const float* __restrict__ cb) {
    int k = blockIdx.x * blockDim.x + threadIdx.x;
    if (k >= KCODES) return;
    const float4* row = reinterpret_cast<const float4*>(cb + (size_t)k * DIM);
    float s = 0.f;
#pragma unroll
    for (int i = 0; i < DIM / 4; i++) {
        float4 v = row[i];
        s += v.x * v.x + v.y * v.y + v.z * v.z + v.w * v.w;
    }
    g_csq[k] = s;
}

__global__ __launch_bounds__(256) void argmin_kernel(const float* __restrict__ x,
                                                     const float* __restrict__ cb) {
    __shared__ float xs[DC][68];   // [d-chunk][token], padded
    __shared__ float cs[DC][68];   // [d-chunk][code],  padded

    const int tid = threadIdx.x;
    const int ty = tid >> 4;       // 0..15 -> token group (4 tokens)
    const int tx = tid & 15;       // 0..15 -> code group  (4 codes)

    const int n0   = blockIdx.x * BT;
    const int b    = n0 >> 10;          // n0 / HW (BT divides HW)
    const int pos0 = n0 & (HW - 1);
    const float* xb = x + (size_t)b * DIM * HW + pos0;

    float best[4];
    int   bidx[4];
#pragma unroll
    for (int i = 0; i < 4; i++) { best[i] = 3.4e38f; bidx[i] = 0; }

    for (int c0 = 0; c0 < KCODES; c0 += BC) {
        float acc[4][4];
#pragma unroll
        for (int i = 0; i < 4; i++)
#pragma unroll
            for (int j = 0; j < 4; j++) acc[i][j] = 0.f;

        for (int d0 = 0; d0 < DIM; d0 += DC) {
            __syncthreads();
            // --- load x tile: 16 dims x 64 tokens, coalesced over tokens ---
#pragma unroll
            for (int kk = 0; kk < 4; kk++) {
                int e   = tid + kk * 256;
                int dd  = e >> 6;
                int tok = e & 63;
                xs[dd][tok] = xb[(size_t)(d0 + dd) * HW + tok];
            }
            // --- load codebook tile: 64 codes x 16 dims (float4 per thread) ---
            {
                int code = tid >> 2;
                int dseg = tid & 3;
                float4 v = *reinterpret_cast<const float4*>(
                    cb + (size_t)(c0 + code) * DIM + d0 + dseg * 4);
                cs[dseg * 4 + 0][code] = v.x;
                cs[dseg * 4 + 1][code] = v.y;
                cs[dseg * 4 + 2][code] = v.z;
                cs[dseg * 4 + 3][code] = v.w;
            }
            __syncthreads();

            // --- 4x4 microtile FMA ---
#pragma unroll
            for (int dd = 0; dd < DC; dd++) {
                float4 av = *reinterpret_cast<const float4*>(&xs[dd][ty * 4]);
                float4 bv = *reinterpret_cast<const float4*>(&cs[dd][tx * 4]);
                float a[4] = {av.x, av.y, av.z, av.w};
                float c[4] = {bv.x, bv.y, bv.z, bv.w};
#pragma unroll
                for (int i = 0; i < 4; i++)
#pragma unroll
                    for (int j = 0; j < 4; j++)
                        acc[i][j] = fmaf(a[i], c[j], acc[i][j]);
            }
        }

        // --- epilogue for this code tile: score = csq - 2*dot ---
#pragma unroll
        for (int j = 0; j < 4; j++) {
            int code = c0 + tx * 4 + j;
            float cq = g_csq[code];
#pragma unroll
            for (int i = 0; i < 4; i++) {
                float dist = fmaf(-2.f, acc[i][j], cq);
                if (dist < best[i]) { best[i] = dist; bidx[i] = code; }
            }
        }
    }

    // --- cross-thread (tx) argmin reduction per token ---
    __shared__ float rd[BT][17];
    __shared__ int   ri[BT][17];
#pragma unroll
    for (int i = 0; i < 4; i++) {
        rd[ty * 4 + i][tx] = best[i];
        ri[ty * 4 + i][tx] = bidx[i];
    }
    __syncthreads();
    if (tid < BT) {
        float bd = rd[tid][0];
        int   bi = ri[tid][0];
#pragma unroll
        for (int t = 1; t < 16; t++) {
            float d = rd[tid][t];
            int   i = ri[tid][t];
            if (d < bd || (d == bd && i < bi)) { bd = d; bi = i; }
        }
        g_idx[n0 + tid] = bi;
    }
}

__global__ void gather_kernel(const float* __restrict__ cb, float* __restrict__ out) {
    int o = blockIdx.x * blockDim.x + threadIdx.x;   // linear output element
    if (o >= NTOK * DIM) return;
    int p = o & (HW - 1);        // h*W + w
    int d = (o >> 10) & (DIM - 1);
    int b = o >> 18;             // / (DIM*HW)
    int n = (b << 10) + p;
    out[o] = cb[(size_t)g_idx[n] * DIM + d];
}

extern "C" void kernel_launch(void* const* d_in, const int* in_sizes, int n_in,
                              void* d_out, int out_size) {
    const float* x  = (const float*)d_in[0];       // 16*256*32*32
    const float* cb = (const float*)d_in[1];       // 4096*256
    float* out = (float*)d_out;

    csq_kernel<<<KCODES / 128, 128>>>(cb);
    argmin_kernel<<<NTOK / BT, 256>>>(x, cb);
    gather_kernel<<<(NTOK * DIM) / 256, 256>>>(cb, out);
}